// round 17
// baseline (speedup 1.0000x reference)
#include <cuda_runtime.h>
#include <math.h>
#include <stdint.h>

#define S_LEN  2048
#define HIDDEN 2048
#define NHEADS 16
#define NKV    4
#define HD     128
#define BATCH  2
#define NQ     (NHEADS*HD)          // 2048
#define NKVD   (NKV*HD)             // 512
#define NTOT   (NQ + 2*NKVD)        // 3072
#define MROWS  (BATCH*S_LEN)        // 4096
#define BHQ    (BATCH*NHEADS)       // 32
#define MASK_N 4194304

// Scratch (device globals)
__device__ float    g_qkv[(size_t)MROWS*NTOT];            // float QKV (rope reads q,k)
__device__ uint32_t g_hsH[(size_t)MROWS*HIDDEN];
__device__ uint32_t g_hsL[(size_t)MROWS*HIDDEN];
__device__ uint32_t g_wH[(size_t)NTOT*HIDDEN];            // q|k|v weights packed
__device__ uint32_t g_wL[(size_t)NTOT*HIDDEN];
__device__ uint32_t g_owH[(size_t)HIDDEN*HIDDEN];
__device__ uint32_t g_owL[(size_t)HIDDEN*HIDDEN];
__device__ uint32_t g_qH[(size_t)BATCH*NHEADS*S_LEN*HD];
__device__ uint32_t g_qL[(size_t)BATCH*NHEADS*S_LEN*HD];
__device__ uint32_t g_kH[(size_t)BATCH*NKV*S_LEN*HD];
__device__ uint32_t g_kL[(size_t)BATCH*NKV*S_LEN*HD];
__device__ uint32_t g_vH[(size_t)MROWS*NKVD];
__device__ uint32_t g_vL[(size_t)MROWS*NKVD];
__device__ float    g_s[(size_t)BHQ*S_LEN*S_LEN];
__device__ uint32_t g_pH[(size_t)BHQ*S_LEN*S_LEN];
__device__ uint32_t g_attnH[(size_t)MROWS*HIDDEN];
__device__ uint32_t g_attnL[(size_t)MROWS*HIDDEN];
__device__ float    g_rc[S_LEN*64];
__device__ float    g_rs[S_LEN*64];

__device__ const float* g_qw_ptr;
__device__ const float* g_ow_ptr;
__device__ const float* g_mask_ptr;

// ---------------------------------------------------------------------------
__global__ void resolve_kernel(const float* c0, const float* c1, const float* c2,
                               int wFirst)
{
    __shared__ float smin[3][256];
    const float* c[3] = {c0, c1, c2};
    const int tid = threadIdx.x;

    for (int i = 0; i < 3; i++) {
        float mn = 3.4e38f;
        for (int e = tid * 1024; e < MASK_N; e += 256 * 1024)
            mn = fminf(mn, c[i][e]);
        smin[i][tid] = mn;
    }
    __syncthreads();
    if (tid == 0) {
        float mn[3];
        for (int i = 0; i < 3; i++) {
            float m = 3.4e38f;
            for (int t = 0; t < 256; t++) m = fminf(m, smin[i][t]);
            mn[i] = m;
        }
        int mi = 0;
        if (mn[1] < mn[mi]) mi = 1;
        if (mn[2] < mn[mi]) mi = 2;
        g_mask_ptr = c[mi];
        const float* nm[2];
        int j = 0;
        for (int i = 0; i < 3; i++)
            if (i != mi) nm[j++] = c[i];
        if (wFirst) { g_qw_ptr = nm[0]; g_ow_ptr = nm[1]; }
        else        { g_qw_ptr = nm[1]; g_ow_ptr = nm[0]; }
    }
}

__global__ void rope_table_kernel()
{
    int idx = blockIdx.x * 256 + threadIdx.x;
    if (idx >= S_LEN * 64) return;
    const int d = idx & 63;
    const int s = idx >> 6;
    double invf = pow(10000.0, -(double)d / 64.0);
    double cs, sn;
    sincos((double)s * invf, &cs, &sn);
    g_rc[idx] = (float)cs;
    g_rs[idx] = (float)sn;
}

// ---------------------------------------------------------------------------
__device__ __forceinline__ void split_tf32(float x, uint32_t& hi, uint32_t& lo)
{
    uint32_t h;
    asm("cvt.rna.tf32.f32 %0, %1;" : "=r"(h) : "f"(x));
    float hf = __uint_as_float(h);
    float lf = x - hf;
    uint32_t l;
    asm("cvt.rna.tf32.f32 %0, %1;" : "=r"(l) : "f"(lf));
    hi = h; lo = l;
}

__device__ __forceinline__ uint32_t to_tf32(float x)
{
    uint32_t h;
    asm("cvt.rna.tf32.f32 %0, %1;" : "=r"(h) : "f"(x));
    return h;
}

__device__ __forceinline__ void mma_tf32(float* c, const uint32_t* a, const uint32_t* b)
{
    asm volatile(
        "mma.sync.aligned.m16n8k8.row.col.f32.tf32.tf32.f32 "
        "{%0,%1,%2,%3}, {%4,%5,%6,%7}, {%8,%9}, {%0,%1,%2,%3};"
        : "+f"(c[0]), "+f"(c[1]), "+f"(c[2]), "+f"(c[3])
        : "r"(a[0]), "r"(a[1]), "r"(a[2]), "r"(a[3]), "r"(b[0]), "r"(b[1]));
}

// ---------------------------------------------------------------------------
// Elementwise pre-split: sel 0 = src param, 1 = g_qw_ptr, 2 = g_ow_ptr.
// 4 elements / thread.
// ---------------------------------------------------------------------------
__global__ void split_plane(const float* __restrict__ src,
                            uint32_t* __restrict__ H, uint32_t* __restrict__ L,
                            int n4, int sel)
{
    if (sel == 1) src = g_qw_ptr;
    else if (sel == 2) src = g_ow_ptr;
    int i = blockIdx.x * 256 + threadIdx.x;
    if (i >= n4) return;
    float4 v = *(const float4*)(src + (size_t)i * 4);
    uint32_t h0, l0, h1, l1, h2, l2, h3, l3;
    split_tf32(v.x, h0, l0); split_tf32(v.y, h1, l1);
    split_tf32(v.z, h2, l2); split_tf32(v.w, h3, l3);
    uint4 hh = {h0, h1, h2, h3};
    uint4 ll = {l0, l1, l2, l3};
    *(uint4*)(H + (size_t)i * 4) = hh;
    *(uint4*)(L + (size_t)i * 4) = ll;
}

// ---------------------------------------------------------------------------
// 3xTF32 GEMM on pre-split planes. Block 64(m) x 128(n), BK=16, 256 threads,
// register-prefetch double buffering.
// MODE 0: QKV proj   A=hs planes, B=w planes; epi: float g_qkv (q,k) / split V
// MODE 1: scores     A=q planes,  B=k planes; epi: scale+mask -> g_s (causal skip)
// MODE 2: PV         A=pH single, B=v planes; epi: split -> attn planes
// MODE 3: O proj     A=attn planes, B=ow planes; epi: float -> out
// ---------------------------------------------------------------------------
template<int MODE>
__global__ __launch_bounds__(256)
void mma_gemm(const float* __restrict__ qb, const float* __restrict__ kb,
              const float* __restrict__ vb, float* __restrict__ Cout)
{
    __shared__ uint32_t AsH[16][68], AsL[16][68];
    __shared__ uint32_t BsH[16][132], BsL[16][132];

    const int tid  = threadIdx.x;
    const int lane = tid & 31;
    const int wid  = tid >> 5;
    const int wm   = wid >> 2;
    const int wn   = wid & 3;
    const int grp  = lane >> 2;
    const int thr  = lane & 3;

    int m0, n0, bh = 0, b = 0, h = 0, kvh = 0, KDIM;
    const uint32_t *AH, *AL = nullptr, *BH, *BL;
    const float* bias = nullptr;
    int lda, ldb, nlocal0 = 0;

    if (MODE == 0) {
        m0 = blockIdx.y * 64;  n0 = blockIdx.x * 128;  KDIM = HIDDEN;
        AH = g_hsH + (size_t)m0 * HIDDEN;  AL = g_hsL + (size_t)m0 * HIDDEN;
        BH = g_wH + (size_t)n0 * HIDDEN;   BL = g_wL + (size_t)n0 * HIDDEN;
        lda = HIDDEN; ldb = HIDDEN;
        if (n0 < NQ)            { bias = qb; nlocal0 = n0; }
        else if (n0 < NQ+NKVD)  { bias = kb; nlocal0 = n0 - NQ; }
        else                    { bias = vb; nlocal0 = n0 - NQ - NKVD; }
    } else if (MODE == 1) {
        m0 = blockIdx.y * 64;  n0 = blockIdx.x * 128;  KDIM = HD;
        if (n0 > m0 + 63) return;
        bh = blockIdx.z; b = bh >> 4; h = bh & 15; kvh = h >> 2;
        AH = g_qH + ((size_t)(b * NHEADS + h) * S_LEN + m0) * HD;
        AL = g_qL + ((size_t)(b * NHEADS + h) * S_LEN + m0) * HD;
        BH = g_kH + ((size_t)(b * NKV + kvh) * S_LEN + n0) * HD;
        BL = g_kL + ((size_t)(b * NKV + kvh) * S_LEN + n0) * HD;
        lda = HD; ldb = HD;
    } else if (MODE == 2) {
        m0 = blockIdx.x * 64;  n0 = 0;
        KDIM = ((m0 >> 7) + 1) * 128;
        bh = blockIdx.y; b = bh >> 4; h = bh & 15; kvh = h >> 2;
        AH = g_pH + (size_t)bh * S_LEN * S_LEN + (size_t)m0 * S_LEN;
        BH = g_vH + (size_t)b * S_LEN * NKVD + kvh * HD;
        BL = g_vL + (size_t)b * S_LEN * NKVD + kvh * HD;
        lda = S_LEN; ldb = NKVD;
    } else {
        m0 = blockIdx.y * 64;  n0 = blockIdx.x * 128;  KDIM = HIDDEN;
        AH = g_attnH + (size_t)m0 * HIDDEN;  AL = g_attnL + (size_t)m0 * HIDDEN;
        BH = g_owH + (size_t)n0 * HIDDEN;    BL = g_owL + (size_t)n0 * HIDDEN;
        lda = HIDDEN; ldb = HIDDEN;
    }

    float acc[2][4][4];
#pragma unroll
    for (int mi = 0; mi < 2; mi++)
#pragma unroll
        for (int ni = 0; ni < 4; ni++)
#pragma unroll
            for (int e = 0; e < 4; e++) acc[mi][ni][e] = 0.f;

    const int arow = tid >> 2;
    const int akq  = (tid & 3) * 4;
    // B thread mapping (two uint4 per plane per thread)
    const int fi0 = tid << 1;

    uint4 paH, paL, pbH[2], pbL[2];

    // Prefetch k0 = 0
    {
        paH = *(const uint4*)(AH + (size_t)arow * lda + akq);
        if (MODE != 2) paL = *(const uint4*)(AL + (size_t)arow * lda + akq);
#pragma unroll
        for (int t = 0; t < 2; t++) {
            int fi = fi0 | t;
            if (MODE == 2) {
                int kr = fi >> 5, nc = (fi & 31) * 4;
                pbH[t] = *(const uint4*)(BH + (size_t)kr * ldb + nc);
                pbL[t] = *(const uint4*)(BL + (size_t)kr * ldb + nc);
            } else {
                int nr = fi >> 2, kq = (fi & 3) * 4;
                pbH[t] = *(const uint4*)(BH + (size_t)nr * ldb + kq);
                pbL[t] = *(const uint4*)(BL + (size_t)nr * ldb + kq);
            }
        }
    }

    for (int k0 = 0; k0 < KDIM; k0 += 16) {
        // Commit prefetched tile to smem
        AsH[akq+0][arow] = paH.x; AsH[akq+1][arow] = paH.y;
        AsH[akq+2][arow] = paH.z; AsH[akq+3][arow] = paH.w;
        if (MODE != 2) {
            AsL[akq+0][arow] = paL.x; AsL[akq+1][arow] = paL.y;
            AsL[akq+2][arow] = paL.z; AsL[akq+3][arow] = paL.w;
        }
#pragma unroll
        for (int t = 0; t < 2; t++) {
            int fi = fi0 | t;
            if (MODE == 2) {
                int kr = fi >> 5, nc = (fi & 31) * 4;
                *(uint4*)&BsH[kr][nc] = pbH[t];
                *(uint4*)&BsL[kr][nc] = pbL[t];
            } else {
                int nr = fi >> 2, kq = (fi & 3) * 4;
                BsH[kq+0][nr] = pbH[t].x; BsH[kq+1][nr] = pbH[t].y;
                BsH[kq+2][nr] = pbH[t].z; BsH[kq+3][nr] = pbH[t].w;
                BsL[kq+0][nr] = pbL[t].x; BsL[kq+1][nr] = pbL[t].y;
                BsL[kq+2][nr] = pbL[t].z; BsL[kq+3][nr] = pbL[t].w;
            }
        }
        __syncthreads();

        // Prefetch next tile
        if (k0 + 16 < KDIM) {
            int kn = k0 + 16;
            paH = *(const uint4*)(AH + (size_t)arow * lda + kn + akq);
            if (MODE != 2) paL = *(const uint4*)(AL + (size_t)arow * lda + kn + akq);
#pragma unroll
            for (int t = 0; t < 2; t++) {
                int fi = fi0 | t;
                if (MODE == 2) {
                    int kr = fi >> 5, nc = (fi & 31) * 4;
                    pbH[t] = *(const uint4*)(BH + (size_t)(kn + kr) * ldb + nc);
                    pbL[t] = *(const uint4*)(BL + (size_t)(kn + kr) * ldb + nc);
                } else {
                    int nr = fi >> 2, kq = (fi & 3) * 4;
                    pbH[t] = *(const uint4*)(BH + (size_t)nr * ldb + kn + kq);
                    pbL[t] = *(const uint4*)(BL + (size_t)nr * ldb + kn + kq);
                }
            }
        }

#pragma unroll
        for (int kk = 0; kk < 16; kk += 8) {
            uint32_t ah[2][4], al[2][4], bhf[4][2], blf[4][2];
#pragma unroll
            for (int mi = 0; mi < 2; mi++) {
                int mb = wm * 32 + mi * 16;
                ah[mi][0] = AsH[kk+thr  ][mb+grp  ];
                ah[mi][1] = AsH[kk+thr  ][mb+grp+8];
                ah[mi][2] = AsH[kk+thr+4][mb+grp  ];
                ah[mi][3] = AsH[kk+thr+4][mb+grp+8];
                if (MODE != 2) {
                    al[mi][0] = AsL[kk+thr  ][mb+grp  ];
                    al[mi][1] = AsL[kk+thr  ][mb+grp+8];
                    al[mi][2] = AsL[kk+thr+4][mb+grp  ];
                    al[mi][3] = AsL[kk+thr+4][mb+grp+8];
                }
            }
#pragma unroll
            for (int ni = 0; ni < 4; ni++) {
                int nb = wn * 32 + ni * 8;
                bhf[ni][0] = BsH[kk+thr  ][nb+grp];
                bhf[ni][1] = BsH[kk+thr+4][nb+grp];
                blf[ni][0] = BsL[kk+thr  ][nb+grp];
                blf[ni][1] = BsL[kk+thr+4][nb+grp];
            }
#pragma unroll
            for (int mi = 0; mi < 2; mi++)
#pragma unroll
                for (int ni = 0; ni < 4; ni++) {
                    mma_tf32(acc[mi][ni], ah[mi], bhf[ni]);
                    mma_tf32(acc[mi][ni], ah[mi], blf[ni]);
                    if (MODE != 2) mma_tf32(acc[mi][ni], al[mi], bhf[ni]);
                }
        }
        __syncthreads();
    }

    const float scale = 0.08838834764831845f;
#pragma unroll
    for (int mi = 0; mi < 2; mi++) {
        int r0 = m0 + wm * 32 + mi * 16 + grp;
#pragma unroll
        for (int ni = 0; ni < 4; ni++) {
            int cb = wn * 32 + ni * 8 + 2 * thr;
#pragma unroll
            for (int e = 0; e < 4; e++) {
                int r = r0 + (e >> 1) * 8;
                int cc = cb + (e & 1);
                float v = acc[mi][ni][e];
                if (MODE == 0) {
                    v += bias[nlocal0 + cc];
                    if (n0 < NQ + NKVD) {
                        g_qkv[(size_t)r * NTOT + n0 + cc] = v;
                    } else {
                        uint32_t hh, ll;
                        split_tf32(v, hh, ll);
                        size_t o = (size_t)r * NKVD + nlocal0 + cc;
                        g_vH[o] = hh; g_vL[o] = ll;
                    }
                } else if (MODE == 1) {
                    int kcol = n0 + cc;
                    g_s[(size_t)bh * S_LEN * S_LEN + (size_t)r * S_LEN + kcol] =
                        v * scale + g_mask_ptr[(size_t)r * S_LEN + kcol];
                } else if (MODE == 2) {
                    uint32_t hh, ll;
                    split_tf32(v, hh, ll);
                    size_t o = ((size_t)(b * S_LEN + r)) * HIDDEN + h * HD + cc;
                    g_attnH[o] = hh; g_attnL[o] = ll;
                } else {
                    Cout[(size_t)r * HIDDEN + n0 + cc] = v;
                }
            }
        }
    }
}

// ---------------------------------------------------------------------------
// Scatter + RoPE via table (NeoX pairing, NEGATED rotation — load-bearing!):
//   out[d]    = x1*c + x2*s ;  out[d+64] = x2*c - x1*s
// Writes split tf32 planes directly. mode 0: q (H=16). mode 1: k (H=4).
// ---------------------------------------------------------------------------
__global__ void scatter_rope(int mode, int H, int col0, int total)
{
    int idx = blockIdx.x * 256 + threadIdx.x;
    if (idx >= total) return;
    const int d = idx & 63;
    const int h = (idx >> 6) % H;
    const int m = idx / (64 * H);
    const int b = m >> 11;
    const int s = m & (S_LEN - 1);

    const float* src = g_qkv + (size_t)m * NTOT + col0 + h * HD;
    const float x1 = src[d];
    const float x2 = src[d + 64];
    const float c  = g_rc[(s << 6) + d];
    const float sf = g_rs[(s << 6) + d];
    const float v1 = x1 * c + x2 * sf;   // NEGATED rotation
    const float v2 = x2 * c - x1 * sf;

    uint32_t h1, l1, h2, l2;
    split_tf32(v1, h1, l1);
    split_tf32(v2, h2, l2);

    size_t base = ((size_t)(b * H + h) * S_LEN + s) * HD;
    uint32_t* dH = (mode == 0) ? g_qH : g_kH;
    uint32_t* dL = (mode == 0) ? g_qL : g_kL;
    dH[base + d] = h1;  dH[base + d + 64] = h2;
    dL[base + d] = l1;  dL[base + d + 64] = l2;
}

// ---------------------------------------------------------------------------
// Softmax: warp per row, causal prefix; writes normalized probs as tf32-hi.
// ---------------------------------------------------------------------------
__global__ void softmax_kernel()
{
    const int warp = threadIdx.x >> 5;
    const int lane = threadIdx.x & 31;
    const int row_id = blockIdx.x * 4 + warp;
    const int bh = row_id >> 11;
    const int q  = row_id & (S_LEN - 1);
    const int kmax = ((q >> 7) + 1) * 128;

    const float* row = g_s + ((size_t)bh * S_LEN + q) * S_LEN;
    uint32_t* prow = g_pH + ((size_t)bh * S_LEN + q) * S_LEN;

    float v[64];
    float m = -3.4e38f;
#pragma unroll
    for (int i = 0; i < 64; i++) {
        const int k = lane + i * 32;
        v[i] = (k < kmax) ? row[k] : -3.4e38f;
        m = fmaxf(m, v[i]);
    }
#pragma unroll
    for (int o = 16; o > 0; o >>= 1)
        m = fmaxf(m, __shfl_xor_sync(0xffffffffu, m, o));

    float l = 0.f;
#pragma unroll
    for (int i = 0; i < 64; i++) {
        v[i] = __expf(v[i] - m);
        l += v[i];
    }
#pragma unroll
    for (int o = 16; o > 0; o >>= 1)
        l += __shfl_xor_sync(0xffffffffu, l, o);

    const float inv = 1.f / l;
#pragma unroll
    for (int i = 0; i < 64; i++) {
        const int k = lane + i * 32;
        if (k < kmax) prow[k] = to_tf32(v[i] * inv);
    }
}

// ---------------------------------------------------------------------------
extern "C" void kernel_launch(void* const* d_in, const int* in_sizes, int n_in,
                              void* d_out, int out_size)
{
    int idx8M = -1, idxQB = -1;
    int idx4M[3] = {1, 2, 8};
    int idx1M[2] = {4, 6};
    int idx512[2] = {5, 7};
    int n4 = 0, n1 = 0, n5 = 0;
    for (int i = 0; i < n_in; i++) {
        switch (in_sizes[i]) {
            case 8388608: idx8M = i; break;
            case 2048:    idxQB = i; break;
            case 4194304: if (n4 < 3) idx4M[n4++] = i; break;
            case 1048576: if (n1 < 2) idx1M[n1++] = i; break;
            case 512:     if (n5 < 2) idx512[n5++] = i; break;
            default: break;
        }
    }
    const float* hs = (const float*)d_in[idx8M];
    const float* qb = (const float*)d_in[idxQB];
    const float* kw = (const float*)d_in[idx1M[0]];
    const float* vw = (const float*)d_in[idx1M[1]];
    const float* kb = (const float*)d_in[idx512[0]];
    const float* vb = (const float*)d_in[idx512[1]];
    const int wFirst = (idx1M[0] < idx512[0]) ? 1 : 0;

    float* out = (float*)d_out;

    uint32_t *hsH, *hsL, *wH, *wL, *owH, *owL;
    cudaGetSymbolAddress((void**)&hsH, g_hsH);
    cudaGetSymbolAddress((void**)&hsL, g_hsL);
    cudaGetSymbolAddress((void**)&wH,  g_wH);
    cudaGetSymbolAddress((void**)&wL,  g_wL);
    cudaGetSymbolAddress((void**)&owH, g_owH);
    cudaGetSymbolAddress((void**)&owL, g_owL);

    // 0) Resolve + rope tables
    resolve_kernel<<<1, 256>>>((const float*)d_in[idx4M[0]],
                               (const float*)d_in[idx4M[1]],
                               (const float*)d_in[idx4M[2]], wFirst);
    rope_table_kernel<<<(S_LEN*64 + 255)/256, 256>>>();

    // 0b) Pre-split operand planes
    {
        int n4a = MROWS * HIDDEN / 4;                 // hs
        split_plane<<<(n4a + 255)/256, 256>>>(hs, hsH, hsL, n4a, 0);
        int n4q = NQ * HIDDEN / 4;                    // q_w (resolved ptr)
        split_plane<<<(n4q + 255)/256, 256>>>(nullptr, wH, wL, n4q, 1);
        int n4k = NKVD * HIDDEN / 4;                  // k_w, v_w
        split_plane<<<(n4k + 255)/256, 256>>>(kw, wH + (size_t)NQ*HIDDEN,
                                              wL + (size_t)NQ*HIDDEN, n4k, 0);
        split_plane<<<(n4k + 255)/256, 256>>>(vw, wH + (size_t)(NQ+NKVD)*HIDDEN,
                                              wL + (size_t)(NQ+NKVD)*HIDDEN, n4k, 0);
        int n4o = HIDDEN * HIDDEN / 4;                // o_w (resolved ptr)
        split_plane<<<(n4o + 255)/256, 256>>>(nullptr, owH, owL, n4o, 2);
    }

    // 1) Fused QKV projection
    mma_gemm<0><<<dim3(NTOT/128, MROWS/64), 256>>>(qb, kb, vb, nullptr);

    // 2) Scatter + RoPE (NEGATED sign), writes split q/k planes
    {
        int tq = MROWS * NHEADS * 64;
        int tk = MROWS * NKV * 64;
        scatter_rope<<<(tq + 255)/256, 256>>>(0, NHEADS, 0,  tq);
        scatter_rope<<<(tk + 255)/256, 256>>>(1, NKV,    NQ, tk);
    }

    // 3) Scores + mask (causal tile skip)
    mma_gemm<1><<<dim3(S_LEN/128, S_LEN/64, BHQ), 256>>>(nullptr, nullptr, nullptr, nullptr);

    // 4) Row softmax -> tf32 probs
    softmax_kernel<<<(BHQ * S_LEN)/4, 128>>>();

    // 5) P @ V (causal k-bound)
    mma_gemm<2><<<dim3(S_LEN/64, BHQ), 256>>>(nullptr, nullptr, nullptr, nullptr);

    // 6) Output projection
    mma_gemm<3><<<dim3(HIDDEN/128, MROWS/64), 256>>>(nullptr, nullptr, nullptr, out);
}